// round 1
// baseline (speedup 1.0000x reference)
#include <cuda_runtime.h>
#include <cuda_bf16.h>
#include <cstdint>

#define N_NODES 50000
#define F_IN 128
#define F_HID 256
#define F_OUT 64

// ---------------- scratch (device globals: no runtime allocation) ----------------
__device__ float g_deg[N_NODES];
__device__ float g_invdeg[N_NODES];
__device__ float g_agg1[(size_t)N_NODES * F_IN];    // 25.6 MB
__device__ float g_h[(size_t)N_NODES * F_HID];      // 51.2 MB
__device__ float g_agg2[(size_t)N_NODES * F_HID];   // 51.2 MB

// ---------------- helpers ----------------
__device__ __forceinline__ void red_add_v4(float4* addr, float4 v) {
    asm volatile("red.global.add.v4.f32 [%0], {%1,%2,%3,%4};"
                 :: "l"(addr), "f"(v.x), "f"(v.y), "f"(v.z), "f"(v.w)
                 : "memory");
}

// ---------------- zero scratch ----------------
__global__ void zero_scratch_kernel() {
    size_t i = (size_t)blockIdx.x * blockDim.x + threadIdx.x;
    size_t stride = (size_t)gridDim.x * blockDim.x;
    for (size_t j = i; j < N_NODES; j += stride) g_deg[j] = 0.0f;
    float4 z = make_float4(0.f, 0.f, 0.f, 0.f);
    float4* a1 = reinterpret_cast<float4*>(g_agg1);
    for (size_t j = i; j < (size_t)N_NODES * F_IN / 4; j += stride) a1[j] = z;
    float4* a2 = reinterpret_cast<float4*>(g_agg2);
    for (size_t j = i; j < (size_t)N_NODES * F_HID / 4; j += stride) a2[j] = z;
}

// ---------------- degree ----------------
__global__ void deg_kernel(const int* __restrict__ dst, int E) {
    int i = blockIdx.x * blockDim.x + threadIdx.x;
    if (i < E) atomicAdd(&g_deg[dst[i]], 1.0f);
}

__global__ void invdeg_kernel() {
    int i = blockIdx.x * blockDim.x + threadIdx.x;
    if (i < N_NODES) g_invdeg[i] = 1.0f / fmaxf(g_deg[i], 1.0f);
}

// ---------------- scatter: warp per edge, vector red atomics ----------------
template <int F>
__global__ void scatter_kernel(const float* __restrict__ feat,
                               const int* __restrict__ src,
                               const int* __restrict__ dst,
                               float* __restrict__ agg, int E) {
    int warp = (blockIdx.x * blockDim.x + threadIdx.x) >> 5;
    if (warp >= E) return;
    int lane = threadIdx.x & 31;
    int s = __ldg(&src[warp]);
    int d = __ldg(&dst[warp]);
    const float4* xs = reinterpret_cast<const float4*>(feat + (size_t)s * F);
    float4* out = reinterpret_cast<float4*>(agg + (size_t)d * F);
#pragma unroll
    for (int j = lane; j < F / 4; j += 32) {
        float4 v = __ldg(&xs[j]);
        red_add_v4(&out[j], v);
    }
}

// ---------------- normalize agg by 1/max(deg,1) ----------------
template <int F>
__global__ void normalize_kernel(float* __restrict__ agg) {
    int i = blockIdx.x * blockDim.x + threadIdx.x;
    constexpr int FV = F / 4;
    if (i >= N_NODES * FV) return;
    int row = i / FV;
    float s = g_invdeg[row];
    float4 v = reinterpret_cast<float4*>(agg)[i];
    v.x *= s; v.y *= s; v.z *= s; v.w *= s;
    reinterpret_cast<float4*>(agg)[i] = v;
}

// ---------------- dual-operand fused GEMM ----------------
// C[M,N] = act( [A0 | A1] (each [M,KH] row-major) @ [W0 ; W1] (each [KH,N] row-major) + bias )
// ACT: 0 = relu, 1 = sigmoid
template <int BM, int BN, int BK, int TM, int TN, int ACT>
__global__ __launch_bounds__((BM / TM) * (BN / TN))
void gemm_dual_kernel(const float* __restrict__ A0, const float* __restrict__ A1, int KH,
                      const float* __restrict__ W0, const float* __restrict__ W1,
                      const float* __restrict__ bias, float* __restrict__ C,
                      int M, int N) {
    constexpr int NT = (BM / TM) * (BN / TN);
    __shared__ float As[BK][BM + 4];
    __shared__ float Ws[BK][BN];

    const int t = threadIdx.x;
    const int tx = t % (BN / TN);
    const int ty = t / (BN / TN);
    const int row0 = blockIdx.y * BM;
    const int col0 = blockIdx.x * BN;

    float acc[TM][TN];
#pragma unroll
    for (int i = 0; i < TM; i++)
#pragma unroll
        for (int j = 0; j < TN; j++) acc[i][j] = 0.0f;

    const int K = 2 * KH;
    for (int k0 = 0; k0 < K; k0 += BK) {
        const float* A = (k0 < KH) ? A0 : A1;
        const float* W = (k0 < KH) ? W0 : W1;
        const int ka = (k0 < KH) ? k0 : (k0 - KH);

        // load A tile: BM x BK, float4 along K
#pragma unroll
        for (int i = t; i < BM * (BK / 4); i += NT) {
            int m = i / (BK / 4);
            int kq = (i % (BK / 4)) * 4;
            int row = row0 + m;
            float4 v = make_float4(0.f, 0.f, 0.f, 0.f);
            if (row < M)
                v = *reinterpret_cast<const float4*>(A + (size_t)row * KH + ka + kq);
            As[kq + 0][m] = v.x;
            As[kq + 1][m] = v.y;
            As[kq + 2][m] = v.z;
            As[kq + 3][m] = v.w;
        }
        // load W tile: BK x BN, float4 along N
#pragma unroll
        for (int i = t; i < BK * (BN / 4); i += NT) {
            int kk = i / (BN / 4);
            int nq = (i % (BN / 4)) * 4;
            float4 v = *reinterpret_cast<const float4*>(W + (size_t)(ka + kk) * N + col0 + nq);
            *reinterpret_cast<float4*>(&Ws[kk][nq]) = v;
        }
        __syncthreads();

#pragma unroll
        for (int kk = 0; kk < BK; kk++) {
            float af[TM], bf[TN];
#pragma unroll
            for (int i = 0; i < TM; i++) af[i] = As[kk][ty * TM + i];
#pragma unroll
            for (int j = 0; j < TN; j++) bf[j] = Ws[kk][tx * TN + j];
#pragma unroll
            for (int i = 0; i < TM; i++)
#pragma unroll
                for (int j = 0; j < TN; j++) acc[i][j] += af[i] * bf[j];
        }
        __syncthreads();
    }

#pragma unroll
    for (int i = 0; i < TM; i++) {
        int row = row0 + ty * TM + i;
        if (row >= M) continue;
#pragma unroll
        for (int j = 0; j < TN; j++) {
            int col = col0 + tx * TN + j;
            float v = acc[i][j] + bias[col];
            if (ACT == 0) v = fmaxf(v, 0.0f);
            else          v = 1.0f / (1.0f + __expf(-v));
            C[(size_t)row * N + col] = v;
        }
    }
}

// ---------------- launch ----------------
extern "C" void kernel_launch(void* const* d_in, const int* in_sizes, int n_in,
                              void* d_out, int out_size) {
    const float* x   = (const float*)d_in[0];
    const int*   ei  = (const int*)d_in[1];
    const float* Wl1 = (const float*)d_in[2];
    const float* Wr1 = (const float*)d_in[3];
    const float* b1  = (const float*)d_in[4];
    const float* Wl2 = (const float*)d_in[5];
    const float* Wr2 = (const float*)d_in[6];
    const float* b2  = (const float*)d_in[7];
    float* out = (float*)d_out;

    const int E = in_sizes[1] / 2;
    const int* src = ei;
    const int* dst = ei + E;

    float *deg_p, *agg1_p, *h_p, *agg2_p;
    cudaGetSymbolAddress((void**)&deg_p,  g_deg);
    cudaGetSymbolAddress((void**)&agg1_p, g_agg1);
    cudaGetSymbolAddress((void**)&h_p,    g_h);
    cudaGetSymbolAddress((void**)&agg2_p, g_agg2);
    (void)deg_p;

    // 1. zero scratch
    zero_scratch_kernel<<<2048, 256>>>();

    // 2. degree + inverse degree
    deg_kernel<<<(E + 255) / 256, 256>>>(dst, E);
    invdeg_kernel<<<(N_NODES + 255) / 256, 256>>>();

    // 3. layer-1 scatter: agg1 += x[src] at dst   (warp per edge)
    {
        int blocks = (E * 32 + 255) / 256;
        scatter_kernel<F_IN><<<blocks, 256>>>(x, src, dst, agg1_p, E);
    }
    // 4. normalize agg1
    {
        int n = N_NODES * (F_IN / 4);
        normalize_kernel<F_IN><<<(n + 255) / 256, 256>>>(agg1_p);
    }
    // 5. h = relu([agg1 | x] @ [Wl1; Wr1] + b1)   M=50000, K=256, N=256
    {
        dim3 grid(F_HID / 128, (N_NODES + 127) / 128);
        gemm_dual_kernel<128, 128, 16, 8, 8, 0><<<grid, 256>>>(
            agg1_p, x, F_IN, Wl1, Wr1, b1, h_p, N_NODES, F_HID);
    }
    // 6. layer-2 scatter: agg2 += h[src] at dst
    {
        int blocks = (E * 32 + 255) / 256;
        scatter_kernel<F_HID><<<blocks, 256>>>(h_p, src, dst, agg2_p, E);
    }
    // 7. normalize agg2
    {
        int n = N_NODES * (F_HID / 4);
        normalize_kernel<F_HID><<<(n + 255) / 256, 256>>>(agg2_p);
    }
    // 8. out = sigmoid([agg2 | h] @ [Wl2; Wr2] + b2)   M=50000, K=512, N=64
    {
        dim3 grid(F_OUT / 64, (N_NODES + 127) / 128);
        gemm_dual_kernel<128, 64, 16, 8, 4, 1><<<grid, 256>>>(
            agg2_p, h_p, F_HID, Wl2, Wr2, b2, out, N_NODES, F_OUT);
    }
}

// round 2
// speedup vs baseline: 1.2904x; 1.2904x over previous
#include <cuda_runtime.h>
#include <cuda_bf16.h>
#include <cstdint>

#define N_NODES 50000
#define MAX_EDGES 800000
#define F_IN 128
#define F_HID 256
#define F_OUT 64

// ---------------- scratch (device globals: no runtime allocation) ----------------
__device__ int   g_degi[N_NODES];
__device__ int   g_cnt[N_NODES];
__device__ int   g_row[N_NODES + 1];
__device__ int   g_csr[MAX_EDGES];
__device__ float g_agg1[(size_t)N_NODES * F_IN];    // 25.6 MB
__device__ float g_h[(size_t)N_NODES * F_HID];      // 51.2 MB
__device__ float g_agg2[(size_t)N_NODES * F_HID];   // 51.2 MB

// ---------------- CSR build ----------------
__global__ void zero_counts_kernel() {
    int i = blockIdx.x * blockDim.x + threadIdx.x;
    if (i < N_NODES) { g_degi[i] = 0; g_cnt[i] = 0; }
}

__global__ void deg_kernel(const int* __restrict__ dst, int E) {
    int i = blockIdx.x * blockDim.x + threadIdx.x;
    if (i < E) atomicAdd(&g_degi[dst[i]], 1);
}

// single-block exclusive scan of g_degi -> g_row
__global__ void scan_kernel(int E) {
    __shared__ int part[1024];
    const int T = 1024;
    const int chunk = (N_NODES + T - 1) / T;
    int t = threadIdx.x;
    int lo = t * chunk;
    int hi = min(lo + chunk, N_NODES);
    int s = 0;
    for (int i = lo; i < hi; i++) s += g_degi[i];
    part[t] = s;
    __syncthreads();
    // Hillis-Steele inclusive scan over 1024 partials
    for (int off = 1; off < T; off <<= 1) {
        int v = (t >= off) ? part[t - off] : 0;
        __syncthreads();
        part[t] += v;
        __syncthreads();
    }
    int running = (t == 0) ? 0 : part[t - 1];
    for (int i = lo; i < hi; i++) {
        g_row[i] = running;
        running += g_degi[i];
    }
    if (t == T - 1) g_row[N_NODES] = E;
}

__global__ void fill_csr_kernel(const int* __restrict__ src,
                                const int* __restrict__ dst, int E) {
    int i = blockIdx.x * blockDim.x + threadIdx.x;
    if (i >= E) return;
    int d = dst[i];
    int pos = g_row[d] + atomicAdd(&g_cnt[d], 1);
    g_csr[pos] = src[i];
}

// ---------------- gather-sum aggregation: warp per node ----------------
template <int F>
__global__ void gather_kernel(const float* __restrict__ feat,
                              float* __restrict__ agg) {
    int node = (blockIdx.x * blockDim.x + threadIdx.x) >> 5;
    if (node >= N_NODES) return;
    int lane = threadIdx.x & 31;
    int start = g_row[node];
    int end   = g_row[node + 1];
    constexpr int V = F / 128;  // float4s per lane

    float4 acc[V];
#pragma unroll
    for (int v = 0; v < V; v++) acc[v] = make_float4(0.f, 0.f, 0.f, 0.f);

    int i = start;
    // 4-neighbor unroll for memory-level parallelism
    for (; i + 4 <= end; i += 4) {
        int s0 = __ldg(&g_csr[i + 0]);
        int s1 = __ldg(&g_csr[i + 1]);
        int s2 = __ldg(&g_csr[i + 2]);
        int s3 = __ldg(&g_csr[i + 3]);
        const float4* x0 = reinterpret_cast<const float4*>(feat + (size_t)s0 * F);
        const float4* x1 = reinterpret_cast<const float4*>(feat + (size_t)s1 * F);
        const float4* x2 = reinterpret_cast<const float4*>(feat + (size_t)s2 * F);
        const float4* x3 = reinterpret_cast<const float4*>(feat + (size_t)s3 * F);
#pragma unroll
        for (int v = 0; v < V; v++) {
            int idx = lane + 32 * v;
            float4 t0 = __ldg(&x0[idx]);
            float4 t1 = __ldg(&x1[idx]);
            float4 t2 = __ldg(&x2[idx]);
            float4 t3 = __ldg(&x3[idx]);
            acc[v].x += t0.x + t1.x + t2.x + t3.x;
            acc[v].y += t0.y + t1.y + t2.y + t3.y;
            acc[v].z += t0.z + t1.z + t2.z + t3.z;
            acc[v].w += t0.w + t1.w + t2.w + t3.w;
        }
    }
    for (; i < end; i++) {
        int s = __ldg(&g_csr[i]);
        const float4* xs = reinterpret_cast<const float4*>(feat + (size_t)s * F);
#pragma unroll
        for (int v = 0; v < V; v++) {
            float4 t = __ldg(&xs[lane + 32 * v]);
            acc[v].x += t.x; acc[v].y += t.y; acc[v].z += t.z; acc[v].w += t.w;
        }
    }

    float inv = 1.0f / fmaxf((float)(end - start), 1.0f);
    float4* out = reinterpret_cast<float4*>(agg + (size_t)node * F);
#pragma unroll
    for (int v = 0; v < V; v++) {
        acc[v].x *= inv; acc[v].y *= inv; acc[v].z *= inv; acc[v].w *= inv;
        out[lane + 32 * v] = acc[v];
    }
}

// ---------------- dual-operand fused GEMM ----------------
// C[M,N] = act( [A0 | A1] (each [M,KH] row-major) @ [W0 ; W1] (each [KH,N] row-major) + bias )
// ACT: 0 = relu, 1 = sigmoid
template <int BM, int BN, int BK, int TM, int TN, int ACT>
__global__ __launch_bounds__((BM / TM) * (BN / TN))
void gemm_dual_kernel(const float* __restrict__ A0, const float* __restrict__ A1, int KH,
                      const float* __restrict__ W0, const float* __restrict__ W1,
                      const float* __restrict__ bias, float* __restrict__ C,
                      int M, int N) {
    constexpr int NT = (BM / TM) * (BN / TN);
    __shared__ float As[BK][BM + 4];
    __shared__ float Ws[BK][BN];

    const int t = threadIdx.x;
    const int tx = t % (BN / TN);
    const int ty = t / (BN / TN);
    const int row0 = blockIdx.y * BM;
    const int col0 = blockIdx.x * BN;

    float acc[TM][TN];
#pragma unroll
    for (int i = 0; i < TM; i++)
#pragma unroll
        for (int j = 0; j < TN; j++) acc[i][j] = 0.0f;

    const int K = 2 * KH;
    for (int k0 = 0; k0 < K; k0 += BK) {
        const float* A = (k0 < KH) ? A0 : A1;
        const float* W = (k0 < KH) ? W0 : W1;
        const int ka = (k0 < KH) ? k0 : (k0 - KH);

        // load A tile: BM x BK, float4 along K
#pragma unroll
        for (int i = t; i < BM * (BK / 4); i += NT) {
            int m = i / (BK / 4);
            int kq = (i % (BK / 4)) * 4;
            int row = row0 + m;
            float4 v = make_float4(0.f, 0.f, 0.f, 0.f);
            if (row < M)
                v = *reinterpret_cast<const float4*>(A + (size_t)row * KH + ka + kq);
            As[kq + 0][m] = v.x;
            As[kq + 1][m] = v.y;
            As[kq + 2][m] = v.z;
            As[kq + 3][m] = v.w;
        }
        // load W tile: BK x BN, float4 along N
#pragma unroll
        for (int i = t; i < BK * (BN / 4); i += NT) {
            int kk = i / (BN / 4);
            int nq = (i % (BN / 4)) * 4;
            float4 v = *reinterpret_cast<const float4*>(W + (size_t)(ka + kk) * N + col0 + nq);
            *reinterpret_cast<float4*>(&Ws[kk][nq]) = v;
        }
        __syncthreads();

#pragma unroll
        for (int kk = 0; kk < BK; kk++) {
            float af[TM], bf[TN];
#pragma unroll
            for (int i = 0; i < TM; i++) af[i] = As[kk][ty * TM + i];
#pragma unroll
            for (int j = 0; j < TN; j++) bf[j] = Ws[kk][tx * TN + j];
#pragma unroll
            for (int i = 0; i < TM; i++)
#pragma unroll
                for (int j = 0; j < TN; j++) acc[i][j] += af[i] * bf[j];
        }
        __syncthreads();
    }

#pragma unroll
    for (int i = 0; i < TM; i++) {
        int row = row0 + ty * TM + i;
        if (row >= M) continue;
#pragma unroll
        for (int j = 0; j < TN; j++) {
            int col = col0 + tx * TN + j;
            float v = acc[i][j] + bias[col];
            if (ACT == 0) v = fmaxf(v, 0.0f);
            else          v = 1.0f / (1.0f + __expf(-v));
            C[(size_t)row * N + col] = v;
        }
    }
}

// ---------------- launch ----------------
extern "C" void kernel_launch(void* const* d_in, const int* in_sizes, int n_in,
                              void* d_out, int out_size) {
    const float* x   = (const float*)d_in[0];
    const int*   ei  = (const int*)d_in[1];
    const float* Wl1 = (const float*)d_in[2];
    const float* Wr1 = (const float*)d_in[3];
    const float* b1  = (const float*)d_in[4];
    const float* Wl2 = (const float*)d_in[5];
    const float* Wr2 = (const float*)d_in[6];
    const float* b2  = (const float*)d_in[7];
    float* out = (float*)d_out;

    const int E = in_sizes[1] / 2;
    const int* src = ei;
    const int* dst = ei + E;

    float *agg1_p, *h_p, *agg2_p;
    cudaGetSymbolAddress((void**)&agg1_p, g_agg1);
    cudaGetSymbolAddress((void**)&h_p,    g_h);
    cudaGetSymbolAddress((void**)&agg2_p, g_agg2);

    // --- CSR build (once; reused for both layers) ---
    zero_counts_kernel<<<(N_NODES + 255) / 256, 256>>>();
    deg_kernel<<<(E + 255) / 256, 256>>>(dst, E);
    scan_kernel<<<1, 1024>>>(E);
    fill_csr_kernel<<<(E + 255) / 256, 256>>>(src, dst, E);

    const int gather_blocks = (N_NODES * 32 + 255) / 256;

    // --- layer 1: agg1 = mean_{j in N(i)} x_j ---
    gather_kernel<F_IN><<<gather_blocks, 256>>>(x, agg1_p);

    // h = relu([agg1 | x] @ [Wl1; Wr1] + b1)   M=50000, K=256, N=256
    {
        dim3 grid(F_HID / 128, (N_NODES + 127) / 128);
        gemm_dual_kernel<128, 128, 16, 8, 8, 0><<<grid, 256>>>(
            agg1_p, x, F_IN, Wl1, Wr1, b1, h_p, N_NODES, F_HID);
    }

    // --- layer 2: agg2 = mean_{j in N(i)} h_j ---
    gather_kernel<F_HID><<<gather_blocks, 256>>>(h_p, agg2_p);

    // out = sigmoid([agg2 | h] @ [Wl2; Wr2] + b2)   M=50000, K=512, N=64
    {
        dim3 grid(F_OUT / 64, (N_NODES + 127) / 128);
        gemm_dual_kernel<128, 64, 16, 8, 4, 1><<<grid, 256>>>(
            agg2_p, h_p, F_HID, Wl2, Wr2, b2, out, N_NODES, F_OUT);
    }
}

// round 3
// speedup vs baseline: 1.3327x; 1.0328x over previous
#include <cuda_runtime.h>
#include <cuda_bf16.h>
#include <cstdint>

#define N_NODES 50000
#define MAX_EDGES 800000
#define F_IN 128
#define F_HID 256
#define F_OUT 64
#define K1 256   // GEMM1 K  = [agg1 | x]
#define K2 512   // GEMM2 K  = [agg2 | h]

typedef __nv_bfloat16 bf16;
typedef __nv_bfloat162 bf162;

// ---------------- scratch (device globals) ----------------
__device__ int   g_degi[N_NODES];
__device__ int   g_cnt[N_NODES];
__device__ int   g_row[N_NODES + 1];
__device__ int   g_csr[MAX_EDGES];
// layer-1 A: [M][K1] = [agg1 (0:128) | x (128:256)], hi/lo bf16
__device__ bf16 g_a1hi[(size_t)N_NODES * K1];
__device__ bf16 g_a1lo[(size_t)N_NODES * K1];
// layer-2 A: [M][K2] = [agg2 (0:256) | h (256:512)], hi/lo bf16
__device__ bf16 g_a2hi[(size_t)N_NODES * K2];
__device__ bf16 g_a2lo[(size_t)N_NODES * K2];
// concatenated weights, hi/lo
__device__ bf16 g_w1hi[K1 * F_HID];
__device__ bf16 g_w1lo[K1 * F_HID];
__device__ bf16 g_w2hi[K2 * F_OUT];
__device__ bf16 g_w2lo[K2 * F_OUT];

// ---------------- helpers ----------------
__device__ __forceinline__ void split_bf16(float v, bf16& hi, bf16& lo) {
    hi = __float2bfloat16_rn(v);
    lo = __float2bfloat16_rn(v - __bfloat162float(hi));
}

// ---------------- CSR build ----------------
__global__ void zero_counts_kernel() {
    int i = blockIdx.x * blockDim.x + threadIdx.x;
    if (i < N_NODES) { g_degi[i] = 0; g_cnt[i] = 0; }
}

__global__ void deg_kernel(const int* __restrict__ dst, int E) {
    int i = blockIdx.x * blockDim.x + threadIdx.x;
    if (i < E) atomicAdd(&g_degi[dst[i]], 1);
}

__global__ void scan_kernel(int E) {
    __shared__ int part[1024];
    const int T = 1024;
    const int chunk = (N_NODES + T - 1) / T;
    int t = threadIdx.x;
    int lo = t * chunk;
    int hi = min(lo + chunk, N_NODES);
    int s = 0;
    for (int i = lo; i < hi; i++) s += g_degi[i];
    part[t] = s;
    __syncthreads();
    for (int off = 1; off < T; off <<= 1) {
        int v = (t >= off) ? part[t - off] : 0;
        __syncthreads();
        part[t] += v;
        __syncthreads();
    }
    int running = (t == 0) ? 0 : part[t - 1];
    for (int i = lo; i < hi; i++) {
        g_row[i] = running;
        running += g_degi[i];
    }
    if (t == T - 1) g_row[N_NODES] = E;
}

__global__ void fill_csr_kernel(const int* __restrict__ src,
                                const int* __restrict__ dst, int E) {
    int i = blockIdx.x * blockDim.x + threadIdx.x;
    if (i >= E) return;
    int d = dst[i];
    int pos = g_row[d] + atomicAdd(&g_cnt[d], 1);
    g_csr[pos] = src[i];
}

// ---------------- operand prep ----------------
// x (f32) -> hi/lo bf16 into A1 cols 128..255
__global__ void split_x_kernel(const float* __restrict__ x) {
    int i = blockIdx.x * blockDim.x + threadIdx.x;   // one float4 each
    if (i >= N_NODES * (F_IN / 4)) return;
    int row = i / (F_IN / 4);
    int c4 = (i % (F_IN / 4)) * 4;
    float4 v = reinterpret_cast<const float4*>(x)[i];
    bf16 h0, h1, h2, h3, l0, l1, l2, l3;
    split_bf16(v.x, h0, l0); split_bf16(v.y, h1, l1);
    split_bf16(v.z, h2, l2); split_bf16(v.w, h3, l3);
    size_t off = (size_t)row * K1 + F_IN + c4;
    *reinterpret_cast<bf162*>(&g_a1hi[off])     = bf162(h0, h1);
    *reinterpret_cast<bf162*>(&g_a1hi[off + 2]) = bf162(h2, h3);
    *reinterpret_cast<bf162*>(&g_a1lo[off])     = bf162(l0, l1);
    *reinterpret_cast<bf162*>(&g_a1lo[off + 2]) = bf162(l2, l3);
}

// W1cat[256][256] = [Wl1 ; Wr1]
__global__ void prep_w1_kernel(const float* __restrict__ Wl,
                               const float* __restrict__ Wr) {
    int i = blockIdx.x * blockDim.x + threadIdx.x;
    if (i >= K1 * F_HID) return;
    int k = i / F_HID, n = i % F_HID;
    float v = (k < F_IN) ? Wl[k * F_HID + n] : Wr[(k - F_IN) * F_HID + n];
    bf16 h, l; split_bf16(v, h, l);
    g_w1hi[i] = h; g_w1lo[i] = l;
}

// W2cat[512][64] = [Wl2 ; Wr2]
__global__ void prep_w2_kernel(const float* __restrict__ Wl,
                               const float* __restrict__ Wr) {
    int i = blockIdx.x * blockDim.x + threadIdx.x;
    if (i >= K2 * F_OUT) return;
    int k = i / F_OUT, n = i % F_OUT;
    float v = (k < F_HID) ? Wl[k * F_OUT + n] : Wr[(k - F_HID) * F_OUT + n];
    bf16 h, l; split_bf16(v, h, l);
    g_w2hi[i] = h; g_w2lo[i] = l;
}

// ---------------- gather 1: x f32 -> mean -> hi/lo into A1 cols 0..127 ----------------
__global__ void gather1_kernel(const float* __restrict__ x) {
    int node = (blockIdx.x * blockDim.x + threadIdx.x) >> 5;
    if (node >= N_NODES) return;
    int lane = threadIdx.x & 31;
    int start = g_row[node], end = g_row[node + 1];

    float4 acc = make_float4(0.f, 0.f, 0.f, 0.f);
    int i = start;
    for (; i + 4 <= end; i += 4) {
        int s0 = __ldg(&g_csr[i]);
        int s1 = __ldg(&g_csr[i + 1]);
        int s2 = __ldg(&g_csr[i + 2]);
        int s3 = __ldg(&g_csr[i + 3]);
        float4 t0 = __ldg(&reinterpret_cast<const float4*>(x + (size_t)s0 * F_IN)[lane]);
        float4 t1 = __ldg(&reinterpret_cast<const float4*>(x + (size_t)s1 * F_IN)[lane]);
        float4 t2 = __ldg(&reinterpret_cast<const float4*>(x + (size_t)s2 * F_IN)[lane]);
        float4 t3 = __ldg(&reinterpret_cast<const float4*>(x + (size_t)s3 * F_IN)[lane]);
        acc.x += t0.x + t1.x + t2.x + t3.x;
        acc.y += t0.y + t1.y + t2.y + t3.y;
        acc.z += t0.z + t1.z + t2.z + t3.z;
        acc.w += t0.w + t1.w + t2.w + t3.w;
    }
    for (; i < end; i++) {
        int s = __ldg(&g_csr[i]);
        float4 t = __ldg(&reinterpret_cast<const float4*>(x + (size_t)s * F_IN)[lane]);
        acc.x += t.x; acc.y += t.y; acc.z += t.z; acc.w += t.w;
    }
    float inv = 1.0f / fmaxf((float)(end - start), 1.0f);
    acc.x *= inv; acc.y *= inv; acc.z *= inv; acc.w *= inv;

    bf16 h0, h1, h2, h3, l0, l1, l2, l3;
    split_bf16(acc.x, h0, l0); split_bf16(acc.y, h1, l1);
    split_bf16(acc.z, h2, l2); split_bf16(acc.w, h3, l3);
    size_t off = (size_t)node * K1 + lane * 4;
    *reinterpret_cast<bf162*>(&g_a1hi[off])     = bf162(h0, h1);
    *reinterpret_cast<bf162*>(&g_a1hi[off + 2]) = bf162(h2, h3);
    *reinterpret_cast<bf162*>(&g_a1lo[off])     = bf162(l0, l1);
    *reinterpret_cast<bf162*>(&g_a1lo[off + 2]) = bf162(l2, l3);
}

// ---------------- gather 2: h (hi/lo bf16, A2 cols 256..511) -> mean -> A2 cols 0..255 ----------------
__device__ __forceinline__ void accum8(float* acc, uint4 u) {
    const bf162* p = reinterpret_cast<const bf162*>(&u);
#pragma unroll
    for (int q = 0; q < 4; q++) {
        float2 f = __bfloat1622float2(p[q]);
        acc[2 * q] += f.x; acc[2 * q + 1] += f.y;
    }
}

__global__ void gather2_kernel() {
    int node = (blockIdx.x * blockDim.x + threadIdx.x) >> 5;
    if (node >= N_NODES) return;
    int lane = threadIdx.x & 31;
    int start = g_row[node], end = g_row[node + 1];

    float acc[8];
#pragma unroll
    for (int q = 0; q < 8; q++) acc[q] = 0.f;

    // h row j lives at g_a2{hi,lo} + j*K2 + 256 ; lane owns 8 cols
    const size_t lane_off = F_HID + lane * 8;
    int i = start;
    for (; i + 2 <= end; i += 2) {
        int s0 = __ldg(&g_csr[i]);
        int s1 = __ldg(&g_csr[i + 1]);
        uint4 h0 = __ldg(reinterpret_cast<const uint4*>(g_a2hi + (size_t)s0 * K2 + lane_off));
        uint4 l0 = __ldg(reinterpret_cast<const uint4*>(g_a2lo + (size_t)s0 * K2 + lane_off));
        uint4 h1 = __ldg(reinterpret_cast<const uint4*>(g_a2hi + (size_t)s1 * K2 + lane_off));
        uint4 l1 = __ldg(reinterpret_cast<const uint4*>(g_a2lo + (size_t)s1 * K2 + lane_off));
        accum8(acc, h0); accum8(acc, l0);
        accum8(acc, h1); accum8(acc, l1);
    }
    for (; i < end; i++) {
        int s = __ldg(&g_csr[i]);
        uint4 h0 = __ldg(reinterpret_cast<const uint4*>(g_a2hi + (size_t)s * K2 + lane_off));
        uint4 l0 = __ldg(reinterpret_cast<const uint4*>(g_a2lo + (size_t)s * K2 + lane_off));
        accum8(acc, h0); accum8(acc, l0);
    }

    float inv = 1.0f / fmaxf((float)(end - start), 1.0f);
    bf16 hv[8], lv[8];
#pragma unroll
    for (int q = 0; q < 8; q++) split_bf16(acc[q] * inv, hv[q], lv[q]);
    size_t off = (size_t)node * K2 + lane * 8;
#pragma unroll
    for (int q = 0; q < 4; q++) {
        *reinterpret_cast<bf162*>(&g_a2hi[off + 2 * q]) = bf162(hv[2 * q], hv[2 * q + 1]);
        *reinterpret_cast<bf162*>(&g_a2lo[off + 2 * q]) = bf162(lv[2 * q], lv[2 * q + 1]);
    }
}

// ---------------- split-bf16 tensor-core GEMM ----------------
// C = act(A @ W + bias), A:[M][KCAT] hi/lo bf16 row-major, W:[KCAT][N] hi/lo bf16 row-major
// C ~= Ah*Wh + Ah*Wl + Al*Wh  (f32 accumulate)
// OUTMODE 0: relu, split-store bf16 into (Chi,Clo) at [row][c_off + col], row stride c_stride
// OUTMODE 1: sigmoid, f32 store into Cf32[row][col], row stride N
__device__ __forceinline__ void mma16816(float* d, const uint32_t* a, const uint32_t* b) {
    asm volatile(
        "mma.sync.aligned.m16n8k16.row.col.f32.bf16.bf16.f32 "
        "{%0,%1,%2,%3}, {%4,%5,%6,%7}, {%8,%9}, {%0,%1,%2,%3};"
        : "+f"(d[0]), "+f"(d[1]), "+f"(d[2]), "+f"(d[3])
        : "r"(a[0]), "r"(a[1]), "r"(a[2]), "r"(a[3]), "r"(b[0]), "r"(b[1]));
}

template <int BM, int BN, int BK, int MW, int NW, int KCAT, int OUTMODE>
__global__ __launch_bounds__(256)
void gemm_mma_kernel(const bf16* __restrict__ Ahi, const bf16* __restrict__ Alo,
                     const bf16* __restrict__ Whi, const bf16* __restrict__ Wlo,
                     const float* __restrict__ bias,
                     float* __restrict__ Cf32, bf16* __restrict__ Chi,
                     bf16* __restrict__ Clo, int c_stride, int c_off,
                     int M, int N) {
    constexpr int BKP = BK + 8;        // bf16 elems per smem row (pad)
    constexpr int WT_M = BM / MW;
    constexpr int WT_N = BN / NW;
    constexpr int MF = WT_M / 16;
    constexpr int NF = WT_N / 8;

    __shared__ bf16 Ash[BM][BKP];
    __shared__ bf16 Asl[BM][BKP];
    __shared__ bf16 Wsh[BN][BKP];
    __shared__ bf16 Wsl[BN][BKP];

    const int t = threadIdx.x;
    const int warp = t >> 5;
    const int lane = t & 31;
    const int wm = warp / NW;
    const int wn = warp % NW;
    const int row0 = blockIdx.y * BM;
    const int col0 = blockIdx.x * BN;

    float acc[MF][NF][4];
#pragma unroll
    for (int a = 0; a < MF; a++)
#pragma unroll
        for (int b = 0; b < NF; b++)
#pragma unroll
            for (int q = 0; q < 4; q++) acc[a][b][q] = 0.f;

    const int r = lane >> 2;
    const int c = (lane & 3) * 2;

    for (int k0 = 0; k0 < KCAT; k0 += BK) {
        // --- load A tile (BM x BK), uint4 = 8 bf16 ---
        constexpr int AV = BM * (BK / 8);
#pragma unroll
        for (int i = t; i < AV; i += 256) {
            int row = i / (BK / 8);
            int q = i % (BK / 8);
            int grow = row0 + row;
            uint4 vh = make_uint4(0, 0, 0, 0), vl = make_uint4(0, 0, 0, 0);
            if (grow < M) {
                size_t g = (size_t)grow * KCAT + k0 + q * 8;
                vh = *reinterpret_cast<const uint4*>(Ahi + g);
                vl = *reinterpret_cast<const uint4*>(Alo + g);
            }
            *reinterpret_cast<uint4*>(&Ash[row][q * 8]) = vh;
            *reinterpret_cast<uint4*>(&Asl[row][q * 8]) = vl;
        }
        // --- load W tile (BK x BN) transposed into [BN][BK] ---
        constexpr int WV = BK * (BN / 8);
#pragma unroll
        for (int i = t; i < WV; i += 256) {
            int k = i / (BN / 8);
            int nq = (i % (BN / 8)) * 8;
            size_t g = (size_t)(k0 + k) * N + col0 + nq;
            uint4 vh = *reinterpret_cast<const uint4*>(Whi + g);
            uint4 vl = *reinterpret_cast<const uint4*>(Wlo + g);
            const bf16* ph = reinterpret_cast<const bf16*>(&vh);
            const bf16* pl = reinterpret_cast<const bf16*>(&vl);
#pragma unroll
            for (int j = 0; j < 8; j++) {
                Wsh[nq + j][k] = ph[j];
                Wsl[nq + j][k] = pl[j];
            }
        }
        __syncthreads();

#pragma unroll
        for (int kk = 0; kk < BK; kk += 16) {
            uint32_t ah[MF][4], al[MF][4];
#pragma unroll
            for (int mf = 0; mf < MF; mf++) {
                int base = wm * WT_M + mf * 16;
#pragma unroll
                for (int j = 0; j < 4; j++) {
                    int rowi = base + r + ((j & 1) << 3);
                    int coli = kk + c + ((j >> 1) << 3);
                    ah[mf][j] = *reinterpret_cast<const uint32_t*>(&Ash[rowi][coli]);
                    al[mf][j] = *reinterpret_cast<const uint32_t*>(&Asl[rowi][coli]);
                }
            }
            uint32_t bh[NF][2], bl[NF][2];
#pragma unroll
            for (int nf = 0; nf < NF; nf++) {
                int n = wn * WT_N + nf * 8 + (lane >> 2);
#pragma unroll
                for (int j = 0; j < 2; j++) {
                    bh[nf][j] = *reinterpret_cast<const uint32_t*>(&Wsh[n][kk + c + j * 8]);
                    bl[nf][j] = *reinterpret_cast<const uint32_t*>(&Wsl[n][kk + c + j * 8]);
                }
            }
#pragma unroll
            for (int mf = 0; mf < MF; mf++)
#pragma unroll
                for (int nf = 0; nf < NF; nf++) {
                    mma16816(acc[mf][nf], ah[mf], bh[nf]);
                    mma16816(acc[mf][nf], ah[mf], bl[nf]);
                    mma16816(acc[mf][nf], al[mf], bh[nf]);
                }
        }
        __syncthreads();
    }

    // --- epilogue ---
#pragma unroll
    for (int mf = 0; mf < MF; mf++) {
#pragma unroll
        for (int nf = 0; nf < NF; nf++) {
#pragma unroll
            for (int p = 0; p < 2; p++) {
                int row = row0 + wm * WT_M + mf * 16 + r + p * 8;
                if (row >= M) continue;
                int colg = col0 + wn * WT_N + nf * 8 + c;
                float v0 = acc[mf][nf][2 * p]     + __ldg(&bias[colg]);
                float v1 = acc[mf][nf][2 * p + 1] + __ldg(&bias[colg + 1]);
                if (OUTMODE == 0) {
                    v0 = fmaxf(v0, 0.f);
                    v1 = fmaxf(v1, 0.f);
                    bf16 h0, h1, l0, l1;
                    split_bf16(v0, h0, l0);
                    split_bf16(v1, h1, l1);
                    size_t off = (size_t)row * c_stride + c_off + colg;
                    *reinterpret_cast<bf162*>(&Chi[off]) = bf162(h0, h1);
                    *reinterpret_cast<bf162*>(&Clo[off]) = bf162(l0, l1);
                } else {
                    v0 = 1.0f / (1.0f + __expf(-v0));
                    v1 = 1.0f / (1.0f + __expf(-v1));
                    size_t off = (size_t)row * N + colg;
                    Cf32[off]     = v0;
                    Cf32[off + 1] = v1;
                }
            }
        }
    }
}

// ---------------- launch ----------------
extern "C" void kernel_launch(void* const* d_in, const int* in_sizes, int n_in,
                              void* d_out, int out_size) {
    const float* x   = (const float*)d_in[0];
    const int*   ei  = (const int*)d_in[1];
    const float* Wl1 = (const float*)d_in[2];
    const float* Wr1 = (const float*)d_in[3];
    const float* b1  = (const float*)d_in[4];
    const float* Wl2 = (const float*)d_in[5];
    const float* Wr2 = (const float*)d_in[6];
    const float* b2  = (const float*)d_in[7];
    float* out = (float*)d_out;

    const int E = in_sizes[1] / 2;
    const int* src = ei;
    const int* dst = ei + E;

    bf16 *a1hi, *a1lo, *a2hi, *a2lo, *w1hi, *w1lo, *w2hi, *w2lo;
    cudaGetSymbolAddress((void**)&a1hi, g_a1hi);
    cudaGetSymbolAddress((void**)&a1lo, g_a1lo);
    cudaGetSymbolAddress((void**)&a2hi, g_a2hi);
    cudaGetSymbolAddress((void**)&a2lo, g_a2lo);
    cudaGetSymbolAddress((void**)&w1hi, g_w1hi);
    cudaGetSymbolAddress((void**)&w1lo, g_w1lo);
    cudaGetSymbolAddress((void**)&w2hi, g_w2hi);
    cudaGetSymbolAddress((void**)&w2lo, g_w2lo);

    // --- CSR build ---
    zero_counts_kernel<<<(N_NODES + 255) / 256, 256>>>();
    deg_kernel<<<(E + 255) / 256, 256>>>(dst, E);
    scan_kernel<<<1, 1024>>>(E);
    fill_csr_kernel<<<(E + 255) / 256, 256>>>(src, dst, E);

    // --- operand prep ---
    split_x_kernel<<<(N_NODES * (F_IN / 4) + 255) / 256, 256>>>(x);
    prep_w1_kernel<<<(K1 * F_HID + 255) / 256, 256>>>(Wl1, Wr1);
    prep_w2_kernel<<<(K2 * F_OUT + 255) / 256, 256>>>(Wl2, Wr2);

    const int gather_blocks = (N_NODES * 32 + 255) / 256;

    // --- layer 1 ---
    gather1_kernel<<<gather_blocks, 256>>>(x);
    {
        // h = relu([agg1|x] @ W1cat + b1), M=50000 K=256 N=256
        dim3 grid(F_HID / 128, (N_NODES + 127) / 128);
        gemm_mma_kernel<128, 128, 32, 2, 4, K1, 0><<<grid, 256>>>(
            a1hi, a1lo, w1hi, w1lo, b1,
            nullptr, a2hi, a2lo, K2, F_HID, N_NODES, F_HID);
    }

    // --- layer 2 ---
    gather2_kernel<<<gather_blocks, 256>>>();
    {
        // out = sigmoid([agg2|h] @ W2cat + b2), M=50000 K=512 N=64
        dim3 grid(F_OUT / 64, (N_NODES + 127) / 128);
        gemm_mma_kernel<128, 64, 32, 4, 2, K2, 1><<<grid, 256>>>(
            a2hi, a2lo, w2hi, w2lo, b2,
            out, nullptr, nullptr, 0, 0, N_NODES, F_OUT);
    }
}

// round 4
// speedup vs baseline: 1.3893x; 1.0424x over previous
#include <cuda_runtime.h>
#include <cuda_bf16.h>
#include <cstdint>

#define N_NODES 50000
#define MAX_EDGES 800000
#define F_IN 128
#define F_HID 256
#define F_OUT 64
#define K1 256   // GEMM1 K = [agg1 | x]
#define N2 128   // GEMM2 N = [y | z]

typedef __nv_bfloat16 bf16;
typedef __nv_bfloat162 bf162;

// ---------------- scratch (device globals) ----------------
__device__ int   g_degi[N_NODES];
__device__ int   g_cnt[N_NODES];
__device__ int   g_row[N_NODES + 1];
__device__ int   g_csr[MAX_EDGES];
// layer-1 A: [M][K1] = [agg1 (0:128) | x (128:256)], hi/lo bf16
__device__ bf16 g_a1hi[(size_t)N_NODES * K1];
__device__ bf16 g_a1lo[(size_t)N_NODES * K1];
// h: [M][F_HID] hi/lo bf16 (GEMM2 A operand only)
__device__ bf16 g_hhi[(size_t)N_NODES * F_HID];
__device__ bf16 g_hlo[(size_t)N_NODES * F_HID];
// yz: [M][128] f32;  cols 0..63 = y = h@W_l2 (to aggregate), 64..127 = z = h@W_r2 + b2
__device__ float g_yz[(size_t)N_NODES * N2];
// weights
__device__ bf16 g_w1hi[K1 * F_HID];
__device__ bf16 g_w1lo[K1 * F_HID];
__device__ bf16 g_w2hi[F_HID * N2];
__device__ bf16 g_w2lo[F_HID * N2];
__device__ float g_bias2[N2];

// ---------------- helpers ----------------
__device__ __forceinline__ void split_bf16(float v, bf16& hi, bf16& lo) {
    hi = __float2bfloat16_rn(v);
    lo = __float2bfloat16_rn(v - __bfloat162float(hi));
}

// ---------------- CSR build ----------------
__global__ void zero_counts_kernel() {
    int i = blockIdx.x * blockDim.x + threadIdx.x;
    if (i < N_NODES) { g_degi[i] = 0; g_cnt[i] = 0; }
}

__global__ void deg_kernel(const int* __restrict__ dst, int E) {
    int i = blockIdx.x * blockDim.x + threadIdx.x;
    if (i < E) atomicAdd(&g_degi[dst[i]], 1);
}

__global__ void scan_kernel(int E) {
    __shared__ int part[1024];
    const int T = 1024;
    const int chunk = (N_NODES + T - 1) / T;
    int t = threadIdx.x;
    int lo = t * chunk;
    int hi = min(lo + chunk, N_NODES);
    int s = 0;
    for (int i = lo; i < hi; i++) s += g_degi[i];
    part[t] = s;
    __syncthreads();
    for (int off = 1; off < T; off <<= 1) {
        int v = (t >= off) ? part[t - off] : 0;
        __syncthreads();
        part[t] += v;
        __syncthreads();
    }
    int running = (t == 0) ? 0 : part[t - 1];
    for (int i = lo; i < hi; i++) {
        g_row[i] = running;
        running += g_degi[i];
    }
    if (t == T - 1) g_row[N_NODES] = E;
}

__global__ void fill_csr_kernel(const int* __restrict__ src,
                                const int* __restrict__ dst, int E) {
    int i = blockIdx.x * blockDim.x + threadIdx.x;
    if (i >= E) return;
    int d = dst[i];
    int pos = g_row[d] + atomicAdd(&g_cnt[d], 1);
    g_csr[pos] = src[i];
}

// ---------------- operand prep ----------------
__global__ void split_x_kernel(const float* __restrict__ x) {
    int i = blockIdx.x * blockDim.x + threadIdx.x;   // one float4 each
    if (i >= N_NODES * (F_IN / 4)) return;
    int row = i / (F_IN / 4);
    int c4 = (i % (F_IN / 4)) * 4;
    float4 v = reinterpret_cast<const float4*>(x)[i];
    bf16 h0, h1, h2, h3, l0, l1, l2, l3;
    split_bf16(v.x, h0, l0); split_bf16(v.y, h1, l1);
    split_bf16(v.z, h2, l2); split_bf16(v.w, h3, l3);
    size_t off = (size_t)row * K1 + F_IN + c4;
    *reinterpret_cast<bf162*>(&g_a1hi[off])     = bf162(h0, h1);
    *reinterpret_cast<bf162*>(&g_a1hi[off + 2]) = bf162(h2, h3);
    *reinterpret_cast<bf162*>(&g_a1lo[off])     = bf162(l0, l1);
    *reinterpret_cast<bf162*>(&g_a1lo[off + 2]) = bf162(l2, l3);
}

// W1cat[256][256] = [Wl1 ; Wr1]
__global__ void prep_w1_kernel(const float* __restrict__ Wl,
                               const float* __restrict__ Wr) {
    int i = blockIdx.x * blockDim.x + threadIdx.x;
    if (i >= K1 * F_HID) return;
    int k = i / F_HID, n = i % F_HID;
    float v = (k < F_IN) ? Wl[k * F_HID + n] : Wr[(k - F_IN) * F_HID + n];
    bf16 h, l; split_bf16(v, h, l);
    g_w1hi[i] = h; g_w1lo[i] = l;
}

// W2cat[256][128]: cols 0..63 = Wl2, cols 64..127 = Wr2.  bias2: [0]*64 ++ b2
__global__ void prep_w2_kernel(const float* __restrict__ Wl,
                               const float* __restrict__ Wr,
                               const float* __restrict__ b2) {
    int i = blockIdx.x * blockDim.x + threadIdx.x;
    if (i < N2) g_bias2[i] = (i < F_OUT) ? 0.0f : b2[i - F_OUT];
    if (i >= F_HID * N2) return;
    int k = i / N2, n = i % N2;
    float v = (n < F_OUT) ? Wl[k * F_OUT + n] : Wr[k * F_OUT + (n - F_OUT)];
    bf16 h, l; split_bf16(v, h, l);
    g_w2hi[i] = h; g_w2lo[i] = l;
}

// ---------------- gather 1: mean of x over neighbors -> hi/lo into A1 cols 0..127 ----------------
__global__ void gather1_kernel(const float* __restrict__ x) {
    int node = (blockIdx.x * blockDim.x + threadIdx.x) >> 5;
    if (node >= N_NODES) return;
    int lane = threadIdx.x & 31;
    int start = g_row[node], end = g_row[node + 1];

    float4 acc = make_float4(0.f, 0.f, 0.f, 0.f);
    int i = start;
    for (; i + 4 <= end; i += 4) {
        int s0 = __ldg(&g_csr[i]);
        int s1 = __ldg(&g_csr[i + 1]);
        int s2 = __ldg(&g_csr[i + 2]);
        int s3 = __ldg(&g_csr[i + 3]);
        float4 t0 = __ldg(&reinterpret_cast<const float4*>(x + (size_t)s0 * F_IN)[lane]);
        float4 t1 = __ldg(&reinterpret_cast<const float4*>(x + (size_t)s1 * F_IN)[lane]);
        float4 t2 = __ldg(&reinterpret_cast<const float4*>(x + (size_t)s2 * F_IN)[lane]);
        float4 t3 = __ldg(&reinterpret_cast<const float4*>(x + (size_t)s3 * F_IN)[lane]);
        acc.x += t0.x + t1.x + t2.x + t3.x;
        acc.y += t0.y + t1.y + t2.y + t3.y;
        acc.z += t0.z + t1.z + t2.z + t3.z;
        acc.w += t0.w + t1.w + t2.w + t3.w;
    }
    for (; i < end; i++) {
        int s = __ldg(&g_csr[i]);
        float4 t = __ldg(&reinterpret_cast<const float4*>(x + (size_t)s * F_IN)[lane]);
        acc.x += t.x; acc.y += t.y; acc.z += t.z; acc.w += t.w;
    }
    float inv = 1.0f / fmaxf((float)(end - start), 1.0f);
    acc.x *= inv; acc.y *= inv; acc.z *= inv; acc.w *= inv;

    bf16 h0, h1, h2, h3, l0, l1, l2, l3;
    split_bf16(acc.x, h0, l0); split_bf16(acc.y, h1, l1);
    split_bf16(acc.z, h2, l2); split_bf16(acc.w, h3, l3);
    size_t off = (size_t)node * K1 + lane * 4;
    *reinterpret_cast<bf162*>(&g_a1hi[off])     = bf162(h0, h1);
    *reinterpret_cast<bf162*>(&g_a1hi[off + 2]) = bf162(h2, h3);
    *reinterpret_cast<bf162*>(&g_a1lo[off])     = bf162(l0, l1);
    *reinterpret_cast<bf162*>(&g_a1lo[off + 2]) = bf162(l2, l3);
}

// ---------------- final: out = sigmoid(mean_agg(y) + z) ----------------
__global__ void final_kernel(float* __restrict__ out) {
    int node = (blockIdx.x * blockDim.x + threadIdx.x) >> 5;
    if (node >= N_NODES) return;
    int lane = threadIdx.x & 31;
    int start = g_row[node], end = g_row[node + 1];

    // lane owns 2 y-columns
    float2 acc = make_float2(0.f, 0.f);
    int i = start;
    for (; i + 4 <= end; i += 4) {
        int s0 = __ldg(&g_csr[i]);
        int s1 = __ldg(&g_csr[i + 1]);
        int s2 = __ldg(&g_csr[i + 2]);
        int s3 = __ldg(&g_csr[i + 3]);
        float2 t0 = __ldg(&reinterpret_cast<const float2*>(g_yz + (size_t)s0 * N2)[lane]);
        float2 t1 = __ldg(&reinterpret_cast<const float2*>(g_yz + (size_t)s1 * N2)[lane]);
        float2 t2 = __ldg(&reinterpret_cast<const float2*>(g_yz + (size_t)s2 * N2)[lane]);
        float2 t3 = __ldg(&reinterpret_cast<const float2*>(g_yz + (size_t)s3 * N2)[lane]);
        acc.x += t0.x + t1.x + t2.x + t3.x;
        acc.y += t0.y + t1.y + t2.y + t3.y;
    }
    for (; i < end; i++) {
        int s = __ldg(&g_csr[i]);
        float2 t = __ldg(&reinterpret_cast<const float2*>(g_yz + (size_t)s * N2)[lane]);
        acc.x += t.x; acc.y += t.y;
    }
    float inv = 1.0f / fmaxf((float)(end - start), 1.0f);
    float2 z = *reinterpret_cast<const float2*>(g_yz + (size_t)node * N2 + F_OUT + lane * 2);
    float v0 = acc.x * inv + z.x;
    float v1 = acc.y * inv + z.y;
    v0 = 1.0f / (1.0f + __expf(-v0));
    v1 = 1.0f / (1.0f + __expf(-v1));
    *reinterpret_cast<float2*>(out + (size_t)node * F_OUT + lane * 2) = make_float2(v0, v1);
}

// ---------------- split-bf16 tensor-core GEMM ----------------
// C = A @ W + bias, A hi/lo bf16 [M][KCAT] row-major, W hi/lo bf16 [KCAT][N] row-major
// C ~= Ah*Wh + Ah*Wl + Al*Wh (f32 accumulate)
// OUTMODE 0: relu, split-store bf16 into (Chi,Clo), row stride c_stride
// OUTMODE 2: linear, f32 store into Cf32, row stride N
__device__ __forceinline__ void mma16816(float* d, const uint32_t* a, const uint32_t* b) {
    asm volatile(
        "mma.sync.aligned.m16n8k16.row.col.f32.bf16.bf16.f32 "
        "{%0,%1,%2,%3}, {%4,%5,%6,%7}, {%8,%9}, {%0,%1,%2,%3};"
        : "+f"(d[0]), "+f"(d[1]), "+f"(d[2]), "+f"(d[3])
        : "r"(a[0]), "r"(a[1]), "r"(a[2]), "r"(a[3]), "r"(b[0]), "r"(b[1]));
}

template <int BM, int BN, int BK, int MW, int NW, int KCAT, int OUTMODE>
__global__ __launch_bounds__(256)
void gemm_mma_kernel(const bf16* __restrict__ Ahi, const bf16* __restrict__ Alo,
                     const bf16* __restrict__ Whi, const bf16* __restrict__ Wlo,
                     const float* __restrict__ bias,
                     float* __restrict__ Cf32, bf16* __restrict__ Chi,
                     bf16* __restrict__ Clo, int c_stride,
                     int M, int N) {
    constexpr int BKP = BK + 8;
    constexpr int WT_M = BM / MW;
    constexpr int WT_N = BN / NW;
    constexpr int MF = WT_M / 16;
    constexpr int NF = WT_N / 8;

    __shared__ bf16 Ash[BM][BKP];
    __shared__ bf16 Asl[BM][BKP];
    __shared__ bf16 Wsh[BN][BKP];
    __shared__ bf16 Wsl[BN][BKP];

    const int t = threadIdx.x;
    const int warp = t >> 5;
    const int lane = t & 31;
    const int wm = warp / NW;
    const int wn = warp % NW;
    const int row0 = blockIdx.y * BM;
    const int col0 = blockIdx.x * BN;

    float acc[MF][NF][4];
#pragma unroll
    for (int a = 0; a < MF; a++)
#pragma unroll
        for (int b = 0; b < NF; b++)
#pragma unroll
            for (int q = 0; q < 4; q++) acc[a][b][q] = 0.f;

    const int r = lane >> 2;
    const int c = (lane & 3) * 2;

    for (int k0 = 0; k0 < KCAT; k0 += BK) {
        constexpr int AV = BM * (BK / 8);
#pragma unroll
        for (int i = t; i < AV; i += 256) {
            int row = i / (BK / 8);
            int q = i % (BK / 8);
            int grow = row0 + row;
            uint4 vh = make_uint4(0, 0, 0, 0), vl = make_uint4(0, 0, 0, 0);
            if (grow < M) {
                size_t g = (size_t)grow * KCAT + k0 + q * 8;
                vh = *reinterpret_cast<const uint4*>(Ahi + g);
                vl = *reinterpret_cast<const uint4*>(Alo + g);
            }
            *reinterpret_cast<uint4*>(&Ash[row][q * 8]) = vh;
            *reinterpret_cast<uint4*>(&Asl[row][q * 8]) = vl;
        }
        constexpr int WV = BK * (BN / 8);
#pragma unroll
        for (int i = t; i < WV; i += 256) {
            int k = i / (BN / 8);
            int nq = (i % (BN / 8)) * 8;
            size_t g = (size_t)(k0 + k) * N + col0 + nq;
            uint4 vh = *reinterpret_cast<const uint4*>(Whi + g);
            uint4 vl = *reinterpret_cast<const uint4*>(Wlo + g);
            const bf16* ph = reinterpret_cast<const bf16*>(&vh);
            const bf16* pl = reinterpret_cast<const bf16*>(&vl);
#pragma unroll
            for (int j = 0; j < 8; j++) {
                Wsh[nq + j][k] = ph[j];
                Wsl[nq + j][k] = pl[j];
            }
        }
        __syncthreads();

#pragma unroll
        for (int kk = 0; kk < BK; kk += 16) {
            uint32_t ah[MF][4], al[MF][4];
#pragma unroll
            for (int mf = 0; mf < MF; mf++) {
                int base = wm * WT_M + mf * 16;
#pragma unroll
                for (int j = 0; j < 4; j++) {
                    int rowi = base + r + ((j & 1) << 3);
                    int coli = kk + c + ((j >> 1) << 3);
                    ah[mf][j] = *reinterpret_cast<const uint32_t*>(&Ash[rowi][coli]);
                    al[mf][j] = *reinterpret_cast<const uint32_t*>(&Asl[rowi][coli]);
                }
            }
            uint32_t bh[NF][2], bl[NF][2];
#pragma unroll
            for (int nf = 0; nf < NF; nf++) {
                int n = wn * WT_N + nf * 8 + (lane >> 2);
#pragma unroll
                for (int j = 0; j < 2; j++) {
                    bh[nf][j] = *reinterpret_cast<const uint32_t*>(&Wsh[n][kk + c + j * 8]);
                    bl[nf][j] = *reinterpret_cast<const uint32_t*>(&Wsl[n][kk + c + j * 8]);
                }
            }
#pragma unroll
            for (int mf = 0; mf < MF; mf++)
#pragma unroll
                for (int nf = 0; nf < NF; nf++) {
                    mma16816(acc[mf][nf], ah[mf], bh[nf]);
                    mma16816(acc[mf][nf], ah[mf], bl[nf]);
                    mma16816(acc[mf][nf], al[mf], bh[nf]);
                }
        }
        __syncthreads();
    }

#pragma unroll
    for (int mf = 0; mf < MF; mf++) {
#pragma unroll
        for (int nf = 0; nf < NF; nf++) {
#pragma unroll
            for (int p = 0; p < 2; p++) {
                int row = row0 + wm * WT_M + mf * 16 + r + p * 8;
                if (row >= M) continue;
                int colg = col0 + wn * WT_N + nf * 8 + c;
                float v0 = acc[mf][nf][2 * p]     + __ldg(&bias[colg]);
                float v1 = acc[mf][nf][2 * p + 1] + __ldg(&bias[colg + 1]);
                if (OUTMODE == 0) {
                    v0 = fmaxf(v0, 0.f);
                    v1 = fmaxf(v1, 0.f);
                    bf16 h0, h1, l0, l1;
                    split_bf16(v0, h0, l0);
                    split_bf16(v1, h1, l1);
                    size_t off = (size_t)row * c_stride + colg;
                    *reinterpret_cast<bf162*>(&Chi[off]) = bf162(h0, h1);
                    *reinterpret_cast<bf162*>(&Clo[off]) = bf162(l0, l1);
                } else {
                    size_t off = (size_t)row * N + colg;
                    Cf32[off]     = v0;
                    Cf32[off + 1] = v1;
                }
            }
        }
    }
}

// ---------------- launch ----------------
extern "C" void kernel_launch(void* const* d_in, const int* in_sizes, int n_in,
                              void* d_out, int out_size) {
    const float* x   = (const float*)d_in[0];
    const int*   ei  = (const int*)d_in[1];
    const float* Wl1 = (const float*)d_in[2];
    const float* Wr1 = (const float*)d_in[3];
    const float* b1  = (const float*)d_in[4];
    const float* Wl2 = (const float*)d_in[5];
    const float* Wr2 = (const float*)d_in[6];
    const float* b2  = (const float*)d_in[7];
    float* out = (float*)d_out;

    const int E = in_sizes[1] / 2;
    const int* src = ei;
    const int* dst = ei + E;

    bf16 *a1hi, *a1lo, *hhi, *hlo, *w1hi, *w1lo, *w2hi, *w2lo;
    float *yz, *bias2;
    cudaGetSymbolAddress((void**)&a1hi, g_a1hi);
    cudaGetSymbolAddress((void**)&a1lo, g_a1lo);
    cudaGetSymbolAddress((void**)&hhi,  g_hhi);
    cudaGetSymbolAddress((void**)&hlo,  g_hlo);
    cudaGetSymbolAddress((void**)&w1hi, g_w1hi);
    cudaGetSymbolAddress((void**)&w1lo, g_w1lo);
    cudaGetSymbolAddress((void**)&w2hi, g_w2hi);
    cudaGetSymbolAddress((void**)&w2lo, g_w2lo);
    cudaGetSymbolAddress((void**)&yz,   g_yz);
    cudaGetSymbolAddress((void**)&bias2, g_bias2);

    // --- CSR build ---
    zero_counts_kernel<<<(N_NODES + 255) / 256, 256>>>();
    deg_kernel<<<(E + 255) / 256, 256>>>(dst, E);
    scan_kernel<<<1, 1024>>>(E);
    fill_csr_kernel<<<(E + 255) / 256, 256>>>(src, dst, E);

    // --- operand prep ---
    split_x_kernel<<<(N_NODES * (F_IN / 4) + 255) / 256, 256>>>(x);
    prep_w1_kernel<<<(K1 * F_HID + 255) / 256, 256>>>(Wl1, Wr1);
    prep_w2_kernel<<<(F_HID * N2 + 255) / 256, 256>>>(Wl2, Wr2, b2);

    const int gather_blocks = (N_NODES * 32 + 255) / 256;

    // --- layer 1 ---
    gather1_kernel<<<gather_blocks, 256>>>(x);
    {
        // h = relu([agg1|x] @ W1cat + b1), M=50000 K=256 N=256
        dim3 grid(F_HID / 128, (N_NODES + 127) / 128);
        gemm_mma_kernel<128, 128, 32, 2, 4, K1, 0><<<grid, 256>>>(
            a1hi, a1lo, w1hi, w1lo, b1,
            nullptr, hhi, hlo, F_HID, N_NODES, F_HID);
    }

    // --- layer 2 reordered: [y|z] = h @ [Wl2|Wr2] + [0|b2] ---
    {
        // M=50000 K=256 N=128
        dim3 grid(N2 / 128, (N_NODES + 127) / 128);
        gemm_mma_kernel<128, 128, 32, 2, 4, F_HID, 2><<<grid, 256>>>(
            hhi, hlo, w2hi, w2lo, bias2,
            yz, nullptr, nullptr, 0, N_NODES, N2);
    }

    // --- final: out = sigmoid(mean_agg(y) + z) ---
    final_kernel<<<gather_blocks, 256>>>(out);
}

// round 5
// speedup vs baseline: 2.3106x; 1.6632x over previous
#include <cuda_runtime.h>
#include <cuda_bf16.h>
#include <cstdint>

#define N_NODES 50000
#define MAX_EDGES 800000
#define F_IN 128
#define F_HID 256
#define F_OUT 64
#define K1 256   // GEMM K for both layers
#define N2 128   // GEMM2 N = [y | z]

typedef __nv_bfloat16 bf16;
typedef __nv_bfloat162 bf162;

// ---------------- scratch (device globals) ----------------
__device__ int   g_degi[N_NODES];
__device__ int   g_cnt[N_NODES];
__device__ int   g_row[N_NODES + 1];
__device__ int   g_csr[MAX_EDGES];
__device__ bf16  g_a1hi[(size_t)N_NODES * K1];   // [agg1 | x] hi
__device__ bf16  g_a1lo[(size_t)N_NODES * K1];   // [agg1 | x] lo
__device__ bf16  g_hhi[(size_t)N_NODES * F_HID];
__device__ bf16  g_hlo[(size_t)N_NODES * F_HID];
__device__ float g_yz[(size_t)N_NODES * N2];     // [y(64) | z(64)]
// transposed weights: W^T[N][K]
__device__ bf16  g_w1thi[F_HID * K1];            // [256][256]
__device__ bf16  g_w1tlo[F_HID * K1];
__device__ bf16  g_w2thi[N2 * F_HID];            // [128][256]
__device__ bf16  g_w2tlo[N2 * F_HID];
__device__ float g_bias2[N2];

// ---------------- helpers ----------------
__device__ __forceinline__ void split_bf16(float v, bf16& hi, bf16& lo) {
    hi = __float2bfloat16_rn(v);
    lo = __float2bfloat16_rn(v - __bfloat162float(hi));
}

__device__ __forceinline__ void cp16(uint32_t dst, const void* src, int src_bytes) {
    asm volatile("cp.async.cg.shared.global [%0], [%1], 16, %2;"
                 :: "r"(dst), "l"(src), "r"(src_bytes) : "memory");
}

__device__ __forceinline__ void mma16816(float* d, const uint32_t* a, const uint32_t* b) {
    asm volatile(
        "mma.sync.aligned.m16n8k16.row.col.f32.bf16.bf16.f32 "
        "{%0,%1,%2,%3}, {%4,%5,%6,%7}, {%8,%9}, {%0,%1,%2,%3};"
        : "+f"(d[0]), "+f"(d[1]), "+f"(d[2]), "+f"(d[3])
        : "r"(a[0]), "r"(a[1]), "r"(a[2]), "r"(a[3]), "r"(b[0]), "r"(b[1]));
}

// ---------------- CSR build ----------------
__global__ void zero_counts_kernel() {
    int i = blockIdx.x * blockDim.x + threadIdx.x;
    if (i < N_NODES) { g_degi[i] = 0; g_cnt[i] = 0; }
}

__global__ void deg_kernel(const int* __restrict__ dst, int E) {
    int i = blockIdx.x * blockDim.x + threadIdx.x;
    if (i < E) atomicAdd(&g_degi[dst[i]], 1);
}

__global__ void scan_kernel(int E) {
    __shared__ int part[1024];
    const int T = 1024;
    const int chunk = (N_NODES + T - 1) / T;
    int t = threadIdx.x;
    int lo = t * chunk;
    int hi = min(lo + chunk, N_NODES);
    int s = 0;
    for (int i = lo; i < hi; i++) s += g_degi[i];
    part[t] = s;
    __syncthreads();
    for (int off = 1; off < T; off <<= 1) {
        int v = (t >= off) ? part[t - off] : 0;
        __syncthreads();
        part[t] += v;
        __syncthreads();
    }
    int running = (t == 0) ? 0 : part[t - 1];
    for (int i = lo; i < hi; i++) {
        g_row[i] = running;
        running += g_degi[i];
    }
    if (t == T - 1) g_row[N_NODES] = E;
}

__global__ void fill_csr_kernel(const int* __restrict__ src,
                                const int* __restrict__ dst, int E) {
    int i = blockIdx.x * blockDim.x + threadIdx.x;
    if (i >= E) return;
    int d = dst[i];
    int pos = g_row[d] + atomicAdd(&g_cnt[d], 1);
    g_csr[pos] = src[i];
}

// ---------------- fused weight prep (transposed) + bias2 ----------------
__global__ void prep_w_kernel(const float* __restrict__ Wl1, const float* __restrict__ Wr1,
                              const float* __restrict__ Wl2, const float* __restrict__ Wr2,
                              const float* __restrict__ b2) {
    int i = blockIdx.x * blockDim.x + threadIdx.x;
    if (i < N2) g_bias2[i] = (i < F_OUT) ? 0.0f : b2[i - F_OUT];
    if (i < F_HID * K1) {
        // W1^T[n][k]: n in [0,256), k in [0,256); W1cat[k][n] = k<128 ? Wl1 : Wr1
        int n = i / K1, k = i % K1;
        float v = (k < F_IN) ? Wl1[k * F_HID + n] : Wr1[(k - F_IN) * F_HID + n];
        bf16 h, l; split_bf16(v, h, l);
        g_w1thi[i] = h; g_w1tlo[i] = l;
    } else {
        int j = i - F_HID * K1;
        if (j < N2 * F_HID) {
            // W2^T[n][k]: n in [0,128), k in [0,256); cols 0..63=Wl2, 64..127=Wr2
            int n = j / F_HID, k = j % F_HID;
            float v = (n < F_OUT) ? Wl2[k * F_OUT + n] : Wr2[k * F_OUT + (n - F_OUT)];
            bf16 h, l; split_bf16(v, h, l);
            g_w2thi[j] = h; g_w2tlo[j] = l;
        }
    }
}

// ---------------- gather1 (+ fused x split): builds [agg1 | x] hi/lo ----------------
__global__ void gather1_kernel(const float* __restrict__ x) {
    int node = (blockIdx.x * blockDim.x + threadIdx.x) >> 5;
    if (node >= N_NODES) return;
    int lane = threadIdx.x & 31;
    int start = g_row[node], end = g_row[node + 1];

    float4 acc = make_float4(0.f, 0.f, 0.f, 0.f);
    int i = start;
    for (; i + 4 <= end; i += 4) {
        int s0 = __ldg(&g_csr[i]);
        int s1 = __ldg(&g_csr[i + 1]);
        int s2 = __ldg(&g_csr[i + 2]);
        int s3 = __ldg(&g_csr[i + 3]);
        float4 t0 = __ldg(&reinterpret_cast<const float4*>(x + (size_t)s0 * F_IN)[lane]);
        float4 t1 = __ldg(&reinterpret_cast<const float4*>(x + (size_t)s1 * F_IN)[lane]);
        float4 t2 = __ldg(&reinterpret_cast<const float4*>(x + (size_t)s2 * F_IN)[lane]);
        float4 t3 = __ldg(&reinterpret_cast<const float4*>(x + (size_t)s3 * F_IN)[lane]);
        acc.x += t0.x + t1.x + t2.x + t3.x;
        acc.y += t0.y + t1.y + t2.y + t3.y;
        acc.z += t0.z + t1.z + t2.z + t3.z;
        acc.w += t0.w + t1.w + t2.w + t3.w;
    }
    for (; i < end; i++) {
        int s = __ldg(&g_csr[i]);
        float4 t = __ldg(&reinterpret_cast<const float4*>(x + (size_t)s * F_IN)[lane]);
        acc.x += t.x; acc.y += t.y; acc.z += t.z; acc.w += t.w;
    }
    float inv = 1.0f / fmaxf((float)(end - start), 1.0f);
    acc.x *= inv; acc.y *= inv; acc.z *= inv; acc.w *= inv;

    bf16 h0, h1, h2, h3, l0, l1, l2, l3;
    split_bf16(acc.x, h0, l0); split_bf16(acc.y, h1, l1);
    split_bf16(acc.z, h2, l2); split_bf16(acc.w, h3, l3);
    size_t off = (size_t)node * K1 + lane * 4;
    *reinterpret_cast<bf162*>(&g_a1hi[off])     = bf162(h0, h1);
    *reinterpret_cast<bf162*>(&g_a1hi[off + 2]) = bf162(h2, h3);
    *reinterpret_cast<bf162*>(&g_a1lo[off])     = bf162(l0, l1);
    *reinterpret_cast<bf162*>(&g_a1lo[off + 2]) = bf162(l2, l3);

    // fused: split x[node] into cols 128..255
    float4 xv = __ldg(&reinterpret_cast<const float4*>(x + (size_t)node * F_IN)[lane]);
    split_bf16(xv.x, h0, l0); split_bf16(xv.y, h1, l1);
    split_bf16(xv.z, h2, l2); split_bf16(xv.w, h3, l3);
    off = (size_t)node * K1 + F_IN + lane * 4;
    *reinterpret_cast<bf162*>(&g_a1hi[off])     = bf162(h0, h1);
    *reinterpret_cast<bf162*>(&g_a1hi[off + 2]) = bf162(h2, h3);
    *reinterpret_cast<bf162*>(&g_a1lo[off])     = bf162(l0, l1);
    *reinterpret_cast<bf162*>(&g_a1lo[off + 2]) = bf162(l2, l3);
}

// ---------------- final: out = sigmoid(mean_agg(y) + z) ----------------
__global__ void final_kernel(float* __restrict__ out) {
    int node = (blockIdx.x * blockDim.x + threadIdx.x) >> 5;
    if (node >= N_NODES) return;
    int lane = threadIdx.x & 31;
    int start = g_row[node], end = g_row[node + 1];

    float2 acc = make_float2(0.f, 0.f);
    int i = start;
    for (; i + 4 <= end; i += 4) {
        int s0 = __ldg(&g_csr[i]);
        int s1 = __ldg(&g_csr[i + 1]);
        int s2 = __ldg(&g_csr[i + 2]);
        int s3 = __ldg(&g_csr[i + 3]);
        float2 t0 = __ldg(&reinterpret_cast<const float2*>(g_yz + (size_t)s0 * N2)[lane]);
        float2 t1 = __ldg(&reinterpret_cast<const float2*>(g_yz + (size_t)s1 * N2)[lane]);
        float2 t2 = __ldg(&reinterpret_cast<const float2*>(g_yz + (size_t)s2 * N2)[lane]);
        float2 t3 = __ldg(&reinterpret_cast<const float2*>(g_yz + (size_t)s3 * N2)[lane]);
        acc.x += t0.x + t1.x + t2.x + t3.x;
        acc.y += t0.y + t1.y + t2.y + t3.y;
    }
    for (; i < end; i++) {
        int s = __ldg(&g_csr[i]);
        float2 t = __ldg(&reinterpret_cast<const float2*>(g_yz + (size_t)s * N2)[lane]);
        acc.x += t.x; acc.y += t.y;
    }
    float inv = 1.0f / fmaxf((float)(end - start), 1.0f);
    float2 z = *reinterpret_cast<const float2*>(g_yz + (size_t)node * N2 + F_OUT + lane * 2);
    float v0 = acc.x * inv + z.x;
    float v1 = acc.y * inv + z.y;
    v0 = 1.0f / (1.0f + __expf(-v0));
    v1 = 1.0f / (1.0f + __expf(-v1));
    *reinterpret_cast<float2*>(out + (size_t)node * F_OUT + lane * 2) = make_float2(v0, v1);
}

// ---------------- pipelined split-bf16 tensor-core GEMM ----------------
// C = A @ W^T^T + bias.  A: hi/lo bf16 [M][KTOT] row-major.  Wt: hi/lo bf16 [N][KTOT].
// C ~= Ah*Wh + Ah*Wl + Al*Wh (f32 accumulate).
// OUTMODE 0: relu, split-store bf16 to (Chi,Clo) row stride c_stride.
// OUTMODE 2: linear, f32 store to Cf32 row stride N.
template <int BM, int BN, int KTOT, int OUTMODE>
__global__ __launch_bounds__(256)
void gemm_mma2_kernel(const bf16* __restrict__ Ahi, const bf16* __restrict__ Alo,
                      const bf16* __restrict__ Wthi, const bf16* __restrict__ Wtlo,
                      const float* __restrict__ bias,
                      float* __restrict__ Cf32, bf16* __restrict__ Chi,
                      bf16* __restrict__ Clo, int c_stride, int M, int N) {
    constexpr int BK = 32;
    constexpr int RS = 40;                      // smem row stride (bf16): 80B, conflict-free
    constexpr int NK = KTOT / BK;
    constexpr int A_ELEMS = 2 * 2 * BM * RS;    // stages x parts
    static_assert(BM == 128 && BN == 128, "tile");

    extern __shared__ char smraw[];
    const uint32_t smA = (uint32_t)__cvta_generic_to_shared(smraw);
    const uint32_t smW = smA + A_ELEMS * 2;     // bytes

    const int t = threadIdx.x;
    const int warp = t >> 5;
    const int lane = t & 31;
    const int wm = warp >> 2;                   // 0..1 (M dir)
    const int wn = warp & 3;                    // 0..3 (N dir)
    const int row0 = blockIdx.y * BM;
    const int col0 = blockIdx.x * BN;
    constexpr int WT_M = 64, WT_N = 32, MF = 4, NF = 4;

    float acc[MF][NF][4];
#pragma unroll
    for (int a = 0; a < MF; a++)
#pragma unroll
        for (int b = 0; b < NF; b++)
#pragma unroll
            for (int q = 0; q < 4; q++) acc[a][b][q] = 0.f;

    // ldmatrix lane-derived offsets
    const int aRow = lane & 15;
    const int aCol = (lane & 16) ? 8 : 0;
    const int bRow = lane & 7;
    const int bCol = (lane & 8) ? 8 : 0;

    auto loadStage = [&](int stage, int k0) {
#pragma unroll
        for (int j = 0; j < 4; j++) {           // A: 1024 16B chunks
            int cidx = t + 256 * j;
            int part = cidx >> 9;
            int rem = cidx & 511;
            int row = rem >> 2;
            int q = rem & 3;
            const bf16* srcb = part ? Alo : Ahi;
            int grow = row0 + row;
            uint32_t d = smA + (((stage * 2 + part) * BM + row) * RS + q * 8) * 2;
            const bf16* s = srcb + ((grow < M) ? ((size_t)grow * KTOT + k0 + q * 8) : 0);
            cp16(d, s, (grow < M) ? 16 : 0);
        }
#pragma unroll
        for (int j = 0; j < 4; j++) {           // W: 1024 16B chunks
            int cidx = t + 256 * j;
            int part = cidx >> 9;
            int rem = cidx & 511;
            int row = rem >> 2;                 // n index
            int q = rem & 3;
            const bf16* srcb = part ? Wtlo : Wthi;
            uint32_t d = smW + (((stage * 2 + part) * BN + row) * RS + q * 8) * 2;
            cp16(d, srcb + (size_t)(col0 + row) * KTOT + k0 + q * 8, 16);
        }
        asm volatile("cp.async.commit_group;" ::: "memory");
    };

    loadStage(0, 0);
    for (int ks = 0; ks < NK; ks++) {
        if (ks + 1 < NK) {
            loadStage((ks + 1) & 1, (ks + 1) * BK);
            asm volatile("cp.async.wait_group 1;" ::: "memory");
        } else {
            asm volatile("cp.async.wait_group 0;" ::: "memory");
        }
        __syncthreads();
        const int st = ks & 1;

#pragma unroll
        for (int kk = 0; kk < BK; kk += 16) {
            uint32_t ah[MF][4], al[MF][4];
#pragma unroll
            for (int mf = 0; mf < MF; mf++) {
                int r = wm * WT_M + mf * 16 + aRow;
                uint32_t ha = smA + (((st * 2 + 0) * BM + r) * RS + kk + aCol) * 2;
                uint32_t la = smA + (((st * 2 + 1) * BM + r) * RS + kk + aCol) * 2;
                asm volatile("ldmatrix.sync.aligned.m8n8.x4.shared.b16 {%0,%1,%2,%3}, [%4];"
                             : "=r"(ah[mf][0]), "=r"(ah[mf][1]), "=r"(ah[mf][2]), "=r"(ah[mf][3])
                             : "r"(ha));
                asm volatile("ldmatrix.sync.aligned.m8n8.x4.shared.b16 {%0,%1,%2,%3}, [%4];"
                             : "=r"(al[mf][0]), "=r"(al[mf][1]), "=r"(al[mf][2]), "=r"(al[mf][3])
                             : "r"(la));
            }
            uint32_t bh[NF][2], bl[NF][2];
#pragma unroll
            for (int nf = 0; nf < NF; nf++) {
                int n = wn * WT_N + nf * 8 + bRow;
                uint32_t hb = smW + (((st * 2 + 0) * BN + n) * RS + kk + bCol) * 2;
                uint32_t lb = smW + (((st * 2 + 1) * BN + n) * RS + kk + bCol) * 2;
                asm volatile("ldmatrix.sync.aligned.m8n8.x2.shared.b16 {%0,%1}, [%2];"
                             : "=r"(bh[nf][0]), "=r"(bh[nf][1]) : "r"(hb));
                asm volatile("ldmatrix.sync.aligned.m8n8.x2.shared.b16 {%0,%1}, [%2];"
                             : "=r"(bl[nf][0]), "=r"(bl[nf][1]) : "r"(lb));
            }
#pragma unroll
            for (int mf = 0; mf < MF; mf++)
#pragma unroll
                for (int nf = 0; nf < NF; nf++) {
                    mma16816(acc[mf][nf], ah[mf], bh[nf]);
                    mma16816(acc[mf][nf], ah[mf], bl[nf]);
                    mma16816(acc[mf][nf], al[mf], bh[nf]);
                }
        }
        __syncthreads();
    }

    // --- epilogue ---
    const int r = lane >> 2;
    const int c = (lane & 3) * 2;
#pragma unroll
    for (int mf = 0; mf < MF; mf++) {
#pragma unroll
        for (int nf = 0; nf < NF; nf++) {
#pragma unroll
            for (int p = 0; p < 2; p++) {
                int row = row0 + wm * WT_M + mf * 16 + r + p * 8;
                if (row >= M) continue;
                int colg = col0 + wn * WT_N + nf * 8 + c;
                float v0 = acc[mf][nf][2 * p]     + __ldg(&bias[colg]);
                float v1 = acc[mf][nf][2 * p + 1] + __ldg(&bias[colg + 1]);
                if (OUTMODE == 0) {
                    v0 = fmaxf(v0, 0.f);
                    v1 = fmaxf(v1, 0.f);
                    bf16 h0, h1, l0, l1;
                    split_bf16(v0, h0, l0);
                    split_bf16(v1, h1, l1);
                    size_t off = (size_t)row * c_stride + colg;
                    *reinterpret_cast<bf162*>(&Chi[off]) = bf162(h0, h1);
                    *reinterpret_cast<bf162*>(&Clo[off]) = bf162(l0, l1);
                } else {
                    size_t off = (size_t)row * N + colg;
                    Cf32[off]     = v0;
                    Cf32[off + 1] = v1;
                }
            }
        }
    }
}

// ---------------- launch ----------------
extern "C" void kernel_launch(void* const* d_in, const int* in_sizes, int n_in,
                              void* d_out, int out_size) {
    const float* x   = (const float*)d_in[0];
    const int*   ei  = (const int*)d_in[1];
    const float* Wl1 = (const float*)d_in[2];
    const float* Wr1 = (const float*)d_in[3];
    const float* b1  = (const float*)d_in[4];
    const float* Wl2 = (const float*)d_in[5];
    const float* Wr2 = (const float*)d_in[6];
    const float* b2  = (const float*)d_in[7];
    float* out = (float*)d_out;

    const int E = in_sizes[1] / 2;
    const int* src = ei;
    const int* dst = ei + E;

    bf16 *a1hi, *a1lo, *hhi, *hlo, *w1thi, *w1tlo, *w2thi, *w2tlo;
    float *yz, *bias2;
    cudaGetSymbolAddress((void**)&a1hi,  g_a1hi);
    cudaGetSymbolAddress((void**)&a1lo,  g_a1lo);
    cudaGetSymbolAddress((void**)&hhi,   g_hhi);
    cudaGetSymbolAddress((void**)&hlo,   g_hlo);
    cudaGetSymbolAddress((void**)&w1thi, g_w1thi);
    cudaGetSymbolAddress((void**)&w1tlo, g_w1tlo);
    cudaGetSymbolAddress((void**)&w2thi, g_w2thi);
    cudaGetSymbolAddress((void**)&w2tlo, g_w2tlo);
    cudaGetSymbolAddress((void**)&yz,    g_yz);
    cudaGetSymbolAddress((void**)&bias2, g_bias2);

    const int SMEM = 2 * (2 * 2 * 128 * 40 * 2);  // A + W regions = 81920 B
    cudaFuncSetAttribute(gemm_mma2_kernel<128, 128, K1, 0>,
                         cudaFuncAttributeMaxDynamicSharedMemorySize, SMEM);
    cudaFuncSetAttribute(gemm_mma2_kernel<128, 128, K1, 2>,
                         cudaFuncAttributeMaxDynamicSharedMemorySize, SMEM);

    // --- CSR build ---
    zero_counts_kernel<<<(N_NODES + 255) / 256, 256>>>();
    deg_kernel<<<(E + 255) / 256, 256>>>(dst, E);
    scan_kernel<<<1, 1024>>>(E);
    fill_csr_kernel<<<(E + 255) / 256, 256>>>(src, dst, E);

    // --- weight prep (fused) ---
    prep_w_kernel<<<(F_HID * K1 + N2 * F_HID + 255) / 256, 256>>>(Wl1, Wr1, Wl2, Wr2, b2);

    const int gather_blocks = (N_NODES * 32 + 255) / 256;

    // --- layer 1: [agg1|x] then h = relu(A1 @ W1cat + b1) ---
    gather1_kernel<<<gather_blocks, 256>>>(x);
    {
        dim3 grid(F_HID / 128, (N_NODES + 127) / 128);
        gemm_mma2_kernel<128, 128, K1, 0><<<grid, 256, SMEM>>>(
            a1hi, a1lo, w1thi, w1tlo, b1,
            nullptr, hhi, hlo, F_HID, N_NODES, F_HID);
    }

    // --- layer 2 reordered: [y|z] = h @ [Wl2|Wr2] + [0|b2] ---
    {
        dim3 grid(N2 / 128, (N_NODES + 127) / 128);
        gemm_mma2_kernel<128, 128, K1, 2><<<grid, 256, SMEM>>>(
            hhi, hlo, w2thi, w2tlo, bias2,
            yz, nullptr, nullptr, 0, N_NODES, N2);
    }

    // --- final: out = sigmoid(mean_agg(y) + z) ---
    final_kernel<<<gather_blocks, 256>>>(out);
}